// round 11
// baseline (speedup 1.0000x reference)
#include <cuda_runtime.h>
#include <math.h>

#define LSEQ 131072
#define NB 4
#define TT 126
#define NTILES ((LSEQ + TT - 1) / TT)   // 1041 (k3)
#define G3X 74              // k3 grid.x: 2 CTAs/SM
#define K1CTAS 74           // k1 grid.x: 2 CTAs/SM
#define T1 128              // k1 tile columns
#define NT1K (LSEQ / T1)    // 1024
#define P1 132              // k1 smem pitch

typedef unsigned long long u64;

// Scratch (no cudaMalloc allowed)
__device__ float g_part[NB * K1CTAS * 3 * 4096];  // partial G0,G1,G2 per CTA
__device__ float g_Z[NB * 5 * 4096];              // Z0,Z1,Z2,Z1t,Z2t
__device__ float g_gd[NB * 3 * 64];
__device__ float g_hd[NB * 3 * 64];
__device__ float g_P[NB * 4096];

// ---------------- packed f32x2 helpers (k3) ----------------
__device__ __forceinline__ u64 dup2(float f) {
    u64 r; asm("mov.b64 %0, {%1, %1};" : "=l"(r) : "f"(f)); return r;
}
__device__ __forceinline__ void fma2(u64& d, u64 a, u64 b) {
    asm("fma.rn.f32x2 %0, %1, %2, %0;" : "+l"(d) : "l"(a), "l"(b));
}
__device__ __forceinline__ float2 unpack2(u64 v) {
    float2 r; asm("mov.b64 {%0, %1}, %2;" : "=f"(r.x), "=f"(r.y) : "l"(v)); return r;
}

// ---------------- cp.async helpers ----------------
__device__ __forceinline__ unsigned s2u(const void* p) {
    unsigned a;
    asm("{ .reg .u64 t; cvta.to.shared.u64 t, %1; cvt.u32.u64 %0, t; }" : "=r"(a) : "l"(p));
    return a;
}
__device__ __forceinline__ void cpa16(unsigned d, const void* s) {
    asm volatile("cp.async.ca.shared.global [%0], [%1], 16;" :: "r"(d), "l"(s) : "memory");
}
__device__ __forceinline__ void cpa4(unsigned d, const void* s, int sz) {
    asm volatile("cp.async.ca.shared.global [%0], [%1], 4, %2;" :: "r"(d), "l"(s), "r"(sz) : "memory");
}
__device__ __forceinline__ void cpa_commit() {
    asm volatile("cp.async.commit_group;" ::: "memory");
}
__device__ __forceinline__ void cpa_wait0() {
    asm volatile("cp.async.wait_group 0;" ::: "memory");
}

// ---------------- tf32 mma.sync (sm_80+ path, NOT 'a'-gated) ----------------
__device__ __forceinline__ void mma8(float* c,
                                     unsigned a0, unsigned a1, unsigned a2, unsigned a3,
                                     unsigned b0, unsigned b1)
{
    asm volatile(
        "mma.sync.aligned.m16n8k8.row.col.f32.tf32.tf32.f32 "
        "{%0,%1,%2,%3}, {%4,%5,%6,%7}, {%8,%9}, {%0,%1,%2,%3};"
        : "+f"(c[0]), "+f"(c[1]), "+f"(c[2]), "+f"(c[3])
        : "r"(a0), "r"(a1), "r"(a2), "r"(a3), "r"(b0), "r"(b1));
}

// ---------------------------------------------------------------------------
// K1 fill: one x tile (64 rows x 130 cols) into dst[c*P1+li].
// ---------------------------------------------------------------------------
__device__ __forceinline__ void k1_fill(float* dst, const float* __restrict__ xb, int t)
{
    const int tid = threadIdx.x;
    const int l0 = t * T1;
    unsigned base = s2u(dst);
    for (int idx = tid; idx < 2048; idx += 256) {
        int c = idx >> 5, ch = idx & 31;
        const float* src = xb + (size_t)c * LSEQ + l0 + ch * 4;
        cpa16(base + (unsigned)((c * P1 + ch * 4) * 4), src);
    }
    for (int idx = tid; idx < 128; idx += 256) {
        int c = idx >> 1, li = T1 + (idx & 1);
        int gl = l0 + li;
        int ok = gl < LSEQ;
        const float* src = xb + (size_t)c * LSEQ + (ok ? gl : 0);
        cpa4(base + (unsigned)((c * P1 + li) * 4), src, ok ? 4 : 0);
    }
}

// ---------------------------------------------------------------------------
// K1: shifted Grams via tf32 mma.sync. Grid (74, NB), 256 threads, 2 CTAs/SM.
// ---------------------------------------------------------------------------
__global__ __launch_bounds__(256, 2)
void k1_mma(const float* __restrict__ x)
{
    extern __shared__ float sm1[];
    float* xs0 = sm1;              // 64*P1 = 8448
    float* xs1 = sm1 + 8448;       // 8448

    const int tid = threadIdx.x, lane = tid & 31, w = tid >> 5;
    const int b = blockIdx.y, jx = blockIdx.x;
    const float* xb = x + (size_t)b * 64 * LSEQ;

    const int m0 = (w >> 1) * 16;
    const int n0 = (w & 1) * 32;
    const int g = lane >> 2, jj = lane & 3;

    float acc[12][4];
#pragma unroll
    for (int i = 0; i < 12; i++)
#pragma unroll
        for (int q = 0; q < 4; q++) acc[i][q] = 0.f;

    int t = jx;
    if (t < NT1K) { k1_fill(xs0, xb, t); }
    cpa_commit();
    cpa_wait0();
    __syncthreads();

    float* cur = xs0;
    float* nxt = xs1;

    for (; t < NT1K; t += K1CTAS) {
        int tn = t + K1CTAS;
        if (tn < NT1K) k1_fill(nxt, xb, tn);
        cpa_commit();

        const float* xc = cur;
#pragma unroll 2
        for (int kc = 0; kc < T1 / 8; kc++) {
            const int k0 = kc * 8;
            const float* ar = xc + (m0 + g) * P1 + k0 + jj;
            unsigned a0 = __float_as_uint(ar[0]);
            unsigned a2 = __float_as_uint(ar[4]);
            unsigned a1 = __float_as_uint(ar[8 * P1]);
            unsigned a3 = __float_as_uint(ar[8 * P1 + 4]);
#pragma unroll
            for (int nt = 0; nt < 4; nt++) {
                const float* br = xc + (n0 + nt * 8 + g) * P1 + k0 + jj;
                unsigned v0 = __float_as_uint(br[0]);
                unsigned v1 = __float_as_uint(br[1]);
                unsigned v2 = __float_as_uint(br[2]);
                unsigned u0 = __float_as_uint(br[4]);
                unsigned u1 = __float_as_uint(br[5]);
                unsigned u2 = __float_as_uint(br[6]);
                mma8(acc[nt * 3 + 0], a0, a1, a2, a3, v0, u0);
                mma8(acc[nt * 3 + 1], a0, a1, a2, a3, v1, u1);
                mma8(acc[nt * 3 + 2], a0, a1, a2, a3, v2, u2);
            }
        }

        cpa_wait0();
        __syncthreads();
        float* tmp = cur; cur = nxt; nxt = tmp;
    }

    float* pb = g_part + ((size_t)(b * K1CTAS + jx) * 3) * 4096;
#pragma unroll
    for (int nt = 0; nt < 4; nt++)
#pragma unroll
        for (int s = 0; s < 3; s++) {
            const float* a = acc[nt * 3 + s];
            int col = n0 + nt * 8 + 2 * jj;
            int r0 = m0 + g;
            pb[s * 4096 + r0 * 64 + col]           = a[0];
            pb[s * 4096 + r0 * 64 + col + 1]       = a[1];
            pb[s * 4096 + (r0 + 8) * 64 + col]     = a[2];
            pb[s * 4096 + (r0 + 8) * 64 + col + 1] = a[3];
        }
}

// ---------------------------------------------------------------------------
// 64x64x64 matmul: C = A @ B (row-major smem); At=true -> C = A^T @ B
// ---------------------------------------------------------------------------
__device__ __forceinline__ void mm64(const float* __restrict__ A,
                                     const float* __restrict__ B,
                                     float* __restrict__ C, int tid, bool At)
{
    const int i0 = (tid >> 4) * 4, j0 = (tid & 15) * 4;
    float acc[4][4] = {};
    for (int k = 0; k < 64; k++) {
        float a[4];
#pragma unroll
        for (int i = 0; i < 4; i++) a[i] = At ? A[k * 64 + i0 + i] : A[(i0 + i) * 64 + k];
        float4 bv = *(const float4*)(B + k * 64 + j0);
        float bb[4] = {bv.x, bv.y, bv.z, bv.w};
#pragma unroll
        for (int i = 0; i < 4; i++)
#pragma unroll
            for (int j = 0; j < 4; j++) acc[i][j] = fmaf(a[i], bb[j], acc[i][j]);
    }
#pragma unroll
    for (int i = 0; i < 4; i++)
#pragma unroll
        for (int j = 0; j < 4; j++) C[(i0 + i) * 64 + j0 + j] = acc[i][j];
}

// ---------------------------------------------------------------------------
// K2a: reduce G_s; gd_s = diag(Wq G_s Wq^T); Z_s = G_s Wk^T (store); hd_s;
// if s>0 also Zt_s = G_s^T Wk^T.
// ---------------------------------------------------------------------------
__global__ __launch_bounds__(256)
void k2a(const float* __restrict__ w_kv, const float* __restrict__ w_q)
{
    extern __shared__ float sm2[];
    float* sG  = sm2;
    float* sWT = sm2 + 4096;
    float* sM  = sm2 + 8192;
    const int tid = threadIdx.x;
    const int s = blockIdx.x, b = blockIdx.y;

    for (int idx = tid; idx < 4096; idx += 256) {
        const float* p = g_part + ((size_t)(b * K1CTAS) * 3 + s) * 4096 + idx;
        float acc = 0.f;
        for (int blk = 0; blk < K1CTAS; blk++) acc += p[(size_t)blk * 3 * 4096];
        sG[idx] = acc;
    }
    for (int idx = tid; idx < 4096; idx += 256)
        sWT[(idx & 63) * 64 + (idx >> 6)] = w_q[idx];
    __syncthreads();

    mm64(sG, sWT, sM, tid, false);          // E = G_s @ Wq^T
    __syncthreads();
    if (tid < 64) {
        float acc = 0.f;
        for (int k = 0; k < 64; k++) acc = fmaf(sWT[k * 64 + tid], sM[k * 64 + tid], acc);
        g_gd[(b * 3 + s) * 64 + tid] = acc;
    }
    __syncthreads();

    for (int idx = tid; idx < 4096; idx += 256)
        sWT[(idx & 63) * 64 + (idx >> 6)] = w_kv[idx];   // Wk rows 0..63
    __syncthreads();

    mm64(sG, sWT, sM, tid, false);          // Z = G_s @ Wk^T
    __syncthreads();
    float* gZ = g_Z + (b * 5 + s) * 4096;
    for (int idx = tid; idx < 4096; idx += 256) gZ[idx] = sM[idx];
    if (tid < 64) {
        float acc = 0.f;
        for (int k = 0; k < 64; k++) acc = fmaf(sWT[k * 64 + tid], sM[k * 64 + tid], acc);
        g_hd[(b * 3 + s) * 64 + tid] = acc;
    }
    __syncthreads();

    if (s > 0) {
        mm64(sG, sWT, sM, tid, true);       // Zt = G_s^T @ Wk^T
        __syncthreads();
        float* gZt = g_Z + (b * 5 + 2 + s) * 4096;
        for (int idx = tid; idx < 4096; idx += 256) gZt[idx] = sM[idx];
    }
}

// ---------------------------------------------------------------------------
// K2b: assemble S (+ edge corrections), norms, softmax, P = Wproj @ attn.
// ---------------------------------------------------------------------------
__global__ __launch_bounds__(256)
void k2b(const float* __restrict__ x,
         const float* __restrict__ w_kv,
         const float* __restrict__ w_kv_dw,
         const float* __restrict__ w_q,
         const float* __restrict__ w_q_dw,
         const float* __restrict__ w_proj,
         const float* __restrict__ temperature)
{
    extern __shared__ float sm3[];
    float* sZ0  = sm3;
    float* sZ1  = sm3 + 4096;
    float* sZ2  = sm3 + 8192;
    float* sZ1t = sm3 + 12288;
    float* sZ2t = sm3 + 16384;
    float* sW   = sm3 + 20480;
    float* sR   = sm3 + 24576;
    float* sS   = sm3 + 28672;
    float* sP   = sm3 + 32768;

    __shared__ float x0s[64], xLs[64], u0s[64], uLs[64], v0s[64], vLs[64];
    __shared__ float aqs[3][64], bks[3][64], nqs[64], nks[64];

    const int tid = threadIdx.x;
    const int b = blockIdx.x;
    const float tempv = temperature[b];

    for (int idx = tid; idx < 5 * 4096; idx += 256) sm3[idx] = g_Z[b * 5 * 4096 + idx];
    for (int idx = tid; idx < 4096; idx += 256) sW[idx] = w_q[idx];
    if (tid < 64) {
        const int c = tid;
        x0s[c] = x[(b * 64 + c) * LSEQ];
        xLs[c] = x[(b * 64 + c) * LSEQ + LSEQ - 1];
#pragma unroll
        for (int e = 0; e < 3; e++) {
            aqs[e][c] = w_q_dw[c * 3 + e];
            bks[e][c] = w_kv_dw[c * 3 + e];
        }
    }
    __syncthreads();

    if (tid < 64) {
        const int c = tid;
        float a0 = 0.f, aL = 0.f, q0 = 0.f, qL = 0.f;
        for (int k = 0; k < 64; k++) {
            float wk = w_kv[c * 64 + k], wq = w_q[c * 64 + k];
            a0 = fmaf(wk, x0s[k], a0);  aL = fmaf(wk, xLs[k], aL);
            q0 = fmaf(wq, x0s[k], q0);  qL = fmaf(wq, xLs[k], qL);
        }
        u0s[c] = a0; uLs[c] = aL; v0s[c] = q0; vLs[c] = qL;
    }
    __syncthreads();

    for (int dd = 0; dd < 3; dd++) {
        for (int idx = tid; idx < 4096; idx += 256) {
            const int i = idx >> 6, j = idx & 63;
            float r;
            if (dd == 0) {
                r = (sZ0[idx] - xLs[i] * uLs[j]) * bks[0][j]
                  + sZ1[idx] * bks[1][j] + sZ2[idx] * bks[2][j];
            } else if (dd == 1) {
                r = sZ1t[idx] * bks[0][j] + sZ0[idx] * bks[1][j] + sZ1[idx] * bks[2][j];
            } else {
                r = sZ2t[idx] * bks[0][j] + sZ1t[idx] * bks[1][j]
                  + (sZ0[idx] - x0s[i] * u0s[j]) * bks[2][j];
            }
            sR[idx] = r;
        }
        __syncthreads();
        {
            const int i0 = (tid >> 4) * 4, j0 = (tid & 15) * 4;
            float acc[4][4] = {};
            for (int k = 0; k < 64; k++) {
                float a[4];
#pragma unroll
                for (int i = 0; i < 4; i++) a[i] = sW[(i0 + i) * 64 + k];
                float4 bv = *(const float4*)(sR + k * 64 + j0);
                float bb[4] = {bv.x, bv.y, bv.z, bv.w};
#pragma unroll
                for (int i = 0; i < 4; i++)
#pragma unroll
                    for (int j = 0; j < 4; j++) acc[i][j] = fmaf(a[i], bb[j], acc[i][j]);
            }
#pragma unroll
            for (int i = 0; i < 4; i++) {
                float scale = aqs[dd][i0 + i];
#pragma unroll
                for (int j = 0; j < 4; j++) {
                    if (dd == 0) sS[(i0 + i) * 64 + j0 + j] = scale * acc[i][j];
                    else         sS[(i0 + i) * 64 + j0 + j] += scale * acc[i][j];
                }
            }
        }
        __syncthreads();
    }

    if (tid < 64) {
        const int c = tid;
        float g0 = g_gd[(b * 3 + 0) * 64 + c], g1 = g_gd[(b * 3 + 1) * 64 + c],
              g2 = g_gd[(b * 3 + 2) * 64 + c];
        float h0 = g_hd[(b * 3 + 0) * 64 + c], h1 = g_hd[(b * 3 + 1) * 64 + c],
              h2 = g_hd[(b * 3 + 2) * 64 + c];
        float am = aqs[0][c], a0 = aqs[1][c], ap = aqs[2][c];
        float bm = bks[0][c], b0 = bks[1][c], bp = bks[2][c];
        float qq = am * am * (g0 - vLs[c] * vLs[c]) + a0 * a0 * g0
                 + ap * ap * (g0 - v0s[c] * v0s[c])
                 + 2.f * (am * a0 + a0 * ap) * g1 + 2.f * am * ap * g2;
        float kk = bm * bm * (h0 - uLs[c] * uLs[c]) + b0 * b0 * h0
                 + bp * bp * (h0 - u0s[c] * u0s[c])
                 + 2.f * (bm * b0 + b0 * bp) * h1 + 2.f * bm * bp * h2;
        nqs[c] = fmaxf(sqrtf(qq), 1e-12f);
        nks[c] = fmaxf(sqrtf(kk), 1e-12f);
    }
    __syncthreads();

    for (int idx = tid; idx < 4096; idx += 256) {
        const int i = idx >> 6, j = idx & 63;
        sS[idx] = tempv * sS[idx] / (nqs[i] * nks[j]);
    }
    __syncthreads();

    if (tid < 64) {
        const int c = tid;
        float m = -1e30f;
        for (int j = 0; j < 64; j++) m = fmaxf(m, sS[c * 64 + j]);
        float sum = 0.f;
        for (int j = 0; j < 64; j++) {
            float e = expf(sS[c * 64 + j] - m);
            sS[c * 64 + j] = e; sum += e;
        }
        float inv = 1.f / sum;
        for (int j = 0; j < 64; j++) sS[c * 64 + j] *= inv;
    }
    __syncthreads();
    for (int idx = tid; idx < 4096; idx += 256) sW[idx] = w_proj[idx];
    __syncthreads();

    mm64(sW, sS, sP, tid, false);
    __syncthreads();
    for (int idx = tid; idx < 4096; idx += 256) g_P[b * 4096 + idx] = sP[idx];
}

// ---------------------------------------------------------------------------
// K3: 256 threads, 2 CTAs/SM. Two buffers; dwconv done in-place (register
// staging) so the x buffer frees right after GEMM1 and hosts the prefetch.
// ---------------------------------------------------------------------------
__device__ __forceinline__ void load_tile_async3(float* dst, const float* xb, int t)
{
    const int tid = threadIdx.x;
    const int l0 = t * TT - 1;
    unsigned base = s2u(dst);
    for (int idx = tid; idx < 64 * 130; idx += 256) {
        int c = idx / 130;
        int li = idx - c * 130;
        int gl = l0 + li;
        int ok = (gl >= 0) && (gl < LSEQ);
        const float* src = xb + (size_t)c * LSEQ + (ok ? gl : 0);
        cpa4(base + (unsigned)((c * 132 + li) * 4), src, ok ? 4 : 0);
    }
}

__global__ __launch_bounds__(256, 2)
void k3_out(const float* __restrict__ x,
            const float* __restrict__ w_kv,
            const float* __restrict__ w_kv_dw,
            float* __restrict__ out)
{
    extern __shared__ float sm4[];
    float* bufA = sm4;            // 8448
    float* bufB = sm4 + 8448;     // 8448
    float* wsv  = sm4 + 16896;    // 4352  [k][o]
    float* ps   = sm4 + 21248;    // 4352  [c][o]
    float* wdv  = sm4 + 25600;    // 192
    // total 25792 floats = 103168 B  (2 CTAs/SM)

    const int tid = threadIdx.x;
    const int b = blockIdx.y;
    const float* xb = x + (size_t)b * 64 * LSEQ;

    for (int idx = tid; idx < 4096; idx += 256) {
        int o = idx >> 6, k = idx & 63;
        wsv[k * 68 + o] = w_kv[(64 + o) * 64 + k];   // Wv rows 64..127
        ps[k * 68 + o]  = g_P[b * 4096 + idx];       // ps[c][o] = P[o][c]
    }
    for (int idx = tid; idx < 192; idx += 256)
        wdv[idx] = w_kv_dw[192 + idx];

    int t = blockIdx.x;
    if (t < NTILES) load_tile_async3(bufA, xb, t);
    cpa_commit();
    cpa_wait0();
    __syncthreads();

    const int o0 = (tid >> 4) * 4;       // 16 o-blocks x 4
    const int lB = (tid & 15) * 8;       // 16 l-blocks x 8
    const int dc  = tid >> 2;            // dwconv: row
    const int dc0 = (tid & 3) * 32;      // dwconv: col chunk

    float* xbuf = bufA;                  // holds x tile
    float* ybuf = bufB;                  // gets yv, then v (in-place)

    for (; t < NTILES; t += G3X) {
        // GEMM1: yv = Wv @ x : read xbuf, write ybuf (cols 0..127)
        {
            u64 acc[4][4];
#pragma unroll
            for (int i = 0; i < 4; i++)
#pragma unroll
                for (int p = 0; p < 4; p++) acc[i][p] = 0ull;
#pragma unroll 4
            for (int k = 0; k < 64; k++) {
                float4 av = *(const float4*)(wsv + k * 68 + o0);
                u64 a0 = dup2(av.x), a1 = dup2(av.y), a2 = dup2(av.z), a3 = dup2(av.w);
                ulonglong2 b01 = *(const ulonglong2*)(xbuf + k * 132 + lB);
                ulonglong2 b23 = *(const ulonglong2*)(xbuf + k * 132 + lB + 4);
                fma2(acc[0][0], a0, b01.x); fma2(acc[0][1], a0, b01.y);
                fma2(acc[0][2], a0, b23.x); fma2(acc[0][3], a0, b23.y);
                fma2(acc[1][0], a1, b01.x); fma2(acc[1][1], a1, b01.y);
                fma2(acc[1][2], a1, b23.x); fma2(acc[1][3], a1, b23.y);
                fma2(acc[2][0], a2, b01.x); fma2(acc[2][1], a2, b01.y);
                fma2(acc[2][2], a2, b23.x); fma2(acc[2][3], a2, b23.y);
                fma2(acc[3][0], a3, b01.x); fma2(acc[3][1], a3, b01.y);
                fma2(acc[3][2], a3, b23.x); fma2(acc[3][3], a3, b23.y);
            }
#pragma unroll
            for (int i = 0; i < 4; i++)
#pragma unroll
                for (int p = 0; p < 4; p++)
                    *(u64*)(ybuf + (o0 + i) * 132 + lB + 2 * p) = acc[i][p];
        }
        __syncthreads();

        // xbuf is now free: prefetch next tile into it
        int tn = t + G3X;
        if (tn < NTILES) load_tile_async3(xbuf, xb, tn);
        cpa_commit();

        // dwconv in-place on ybuf: stage reads to regs, sync, write back
        {
            float v[34];
            const float* yr = ybuf + dc * 132 + dc0;
#pragma unroll
            for (int i = 0; i < 34; i++) v[i] = yr[i];   // cols <= 129 in-buffer
            __syncthreads();
            float wd0 = wdv[dc * 3], wd1 = wdv[dc * 3 + 1], wd2 = wdv[dc * 3 + 2];
            float* vw = ybuf + dc * 132 + dc0;
#pragma unroll
            for (int i = 0; i < 32; i += 2) {
                if (dc0 + i < TT) {
                    float2 o2;
                    o2.x = wd0 * v[i]     + wd1 * v[i + 1] + wd2 * v[i + 2];
                    o2.y = wd0 * v[i + 1] + wd1 * v[i + 2] + wd2 * v[i + 3];
                    *(float2*)(vw + i) = o2;
                }
            }
        }
        __syncthreads();

        // GEMM2: out = P @ v : read ybuf, store to gmem
        {
            u64 acc[4][4];
#pragma unroll
            for (int i = 0; i < 4; i++)
#pragma unroll
                for (int p = 0; p < 4; p++) acc[i][p] = 0ull;
#pragma unroll 4
            for (int c = 0; c < 64; c++) {
                float4 av = *(const float4*)(ps + c * 68 + o0);
                u64 a0 = dup2(av.x), a1 = dup2(av.y), a2 = dup2(av.z), a3 = dup2(av.w);
                ulonglong2 b01 = *(const ulonglong2*)(ybuf + c * 132 + lB);
                ulonglong2 b23 = *(const ulonglong2*)(ybuf + c * 132 + lB + 4);
                fma2(acc[0][0], a0, b01.x); fma2(acc[0][1], a0, b01.y);
                fma2(acc[0][2], a0, b23.x); fma2(acc[0][3], a0, b23.y);
                fma2(acc[1][0], a1, b01.x); fma2(acc[1][1], a1, b01.y);
                fma2(acc[1][2], a1, b23.x); fma2(acc[1][3], a1, b23.y);
                fma2(acc[2][0], a2, b01.x); fma2(acc[2][1], a2, b01.y);
                fma2(acc[2][2], a2, b23.x); fma2(acc[2][3], a2, b23.y);
                fma2(acc[3][0], a3, b01.x); fma2(acc[3][1], a3, b01.y);
                fma2(acc[3][2], a3, b23.x); fma2(acc[3][3], a3, b23.y);
            }
            const int gl = t * TT + lB;
#pragma unroll
            for (int i = 0; i < 4; i++) {
                float* op = out + (size_t)(b * 64 + o0 + i) * LSEQ;
#pragma unroll
                for (int p = 0; p < 4; p++) {
                    int lp = lB + 2 * p;
                    if (lp + 1 < TT && gl + 2 * p + 1 < LSEQ)
                        *(float2*)(op + gl + 2 * p) = unpack2(acc[i][p]);
                }
            }
        }

        cpa_wait0();
        __syncthreads();
        float* tmp = xbuf; xbuf = ybuf; ybuf = tmp;   // next x is in old ybuf? no:
        // prefetch went into old xbuf; swap back so xbuf stays the x holder
        tmp = xbuf; xbuf = ybuf; ybuf = tmp;
    }
}

// ---------------------------------------------------------------------------
extern "C" void kernel_launch(void* const* d_in, const int* in_sizes, int n_in,
                              void* d_out, int out_size)
{
    const float* x           = (const float*)d_in[0];
    const float* w_kv        = (const float*)d_in[1];
    const float* w_kv_dw     = (const float*)d_in[2];
    const float* w_q         = (const float*)d_in[3];
    const float* w_q_dw      = (const float*)d_in[4];
    const float* w_proj      = (const float*)d_in[5];
    const float* temperature = (const float*)d_in[6];
    float* out = (float*)d_out;

    const int SM1  = 2 * 8448 * 4;      // 67584 (2 CTAs/SM)
    const int SM2A = 3 * 4096 * 4;
    const int SM2B = 9 * 4096 * 4;
    const int SM3  = 25792 * 4;         // 103168 (2 CTAs/SM)
    cudaFuncSetAttribute(k1_mma, cudaFuncAttributeMaxDynamicSharedMemorySize, SM1);
    cudaFuncSetAttribute(k2a,    cudaFuncAttributeMaxDynamicSharedMemorySize, SM2A);
    cudaFuncSetAttribute(k2b,    cudaFuncAttributeMaxDynamicSharedMemorySize, SM2B);
    cudaFuncSetAttribute(k3_out, cudaFuncAttributeMaxDynamicSharedMemorySize, SM3);

    k1_mma<<<dim3(K1CTAS, NB), 256, SM1>>>(x);
    k2a<<<dim3(3, NB), 256, SM2A>>>(w_kv, w_q);
    k2b<<<NB, 256, SM2B>>>(x, w_kv, w_kv_dw, w_q, w_q_dw, w_proj, temperature);
    k3_out<<<dim3(G3X, NB), 256, SM3>>>(x, w_kv, w_kv_dw, out);
}

// round 13
// speedup vs baseline: 1.3513x; 1.3513x over previous
#include <cuda_runtime.h>
#include <math.h>

#define LSEQ 131072
#define NB 4
#define TT 126
#define NTILES ((LSEQ + TT - 1) / TT)   // 1041 (k3)
#define G3X 37              // k3 persistent grid.x (1 CTA/SM)
#define K1CTAS 37           // k1 persistent grid.x
#define T1 128              // k1 tile columns
#define NT1K (LSEQ / T1)    // 1024
#define P1 132              // k1 smem pitch

typedef unsigned long long u64;

// Scratch (no cudaMalloc allowed)
__device__ float g_part[NB * K1CTAS * 3 * 4096];  // partial G0,G1,G2 per CTA
__device__ float g_Z[NB * 5 * 4096];              // Z0,Z1,Z2,Z1t,Z2t
__device__ float g_gd[NB * 3 * 64];
__device__ float g_hd[NB * 3 * 64];
__device__ float g_P[NB * 4096];

// ---------------- packed f32x2 helpers (k3) ----------------
__device__ __forceinline__ u64 dup2(float f) {
    u64 r; asm("mov.b64 %0, {%1, %1};" : "=l"(r) : "f"(f)); return r;
}
__device__ __forceinline__ void fma2(u64& d, u64 a, u64 b) {
    asm("fma.rn.f32x2 %0, %1, %2, %0;" : "+l"(d) : "l"(a), "l"(b));
}
__device__ __forceinline__ float2 unpack2(u64 v) {
    float2 r; asm("mov.b64 {%0, %1}, %2;" : "=f"(r.x), "=f"(r.y) : "l"(v)); return r;
}

// ---------------- cp.async helpers ----------------
__device__ __forceinline__ unsigned s2u(const void* p) {
    unsigned a;
    asm("{ .reg .u64 t; cvta.to.shared.u64 t, %1; cvt.u32.u64 %0, t; }" : "=r"(a) : "l"(p));
    return a;
}
__device__ __forceinline__ void cpa16(unsigned d, const void* s) {
    asm volatile("cp.async.ca.shared.global [%0], [%1], 16;" :: "r"(d), "l"(s) : "memory");
}
__device__ __forceinline__ void cpa4(unsigned d, const void* s, int sz) {
    asm volatile("cp.async.ca.shared.global [%0], [%1], 4, %2;" :: "r"(d), "l"(s), "r"(sz) : "memory");
}
__device__ __forceinline__ void cpa_commit() {
    asm volatile("cp.async.commit_group;" ::: "memory");
}
__device__ __forceinline__ void cpa_wait0() {
    asm volatile("cp.async.wait_group 0;" ::: "memory");
}

// ---------------- tf32 mma.sync (sm_80+ path, NOT 'a'-gated) ----------------
__device__ __forceinline__ void mma8(float* c,
                                     unsigned a0, unsigned a1, unsigned a2, unsigned a3,
                                     unsigned b0, unsigned b1)
{
    asm volatile(
        "mma.sync.aligned.m16n8k8.row.col.f32.tf32.tf32.f32 "
        "{%0,%1,%2,%3}, {%4,%5,%6,%7}, {%8,%9}, {%0,%1,%2,%3};"
        : "+f"(c[0]), "+f"(c[1]), "+f"(c[2]), "+f"(c[3])
        : "r"(a0), "r"(a1), "r"(a2), "r"(a3), "r"(b0), "r"(b1));
}

// ---------------------------------------------------------------------------
// K1 fill: one x tile (64 rows x 130 cols) into dst[c*P1+li].
// ---------------------------------------------------------------------------
__device__ __forceinline__ void k1_fill(float* dst, const float* __restrict__ xb, int t)
{
    const int tid = threadIdx.x;
    const int l0 = t * T1;
    unsigned base = s2u(dst);
    for (int idx = tid; idx < 2048; idx += 256) {
        int c = idx >> 5, ch = idx & 31;
        const float* src = xb + (size_t)c * LSEQ + l0 + ch * 4;
        cpa16(base + (unsigned)((c * P1 + ch * 4) * 4), src);
    }
    for (int idx = tid; idx < 128; idx += 256) {
        int c = idx >> 1, li = T1 + (idx & 1);
        int gl = l0 + li;
        int ok = gl < LSEQ;
        const float* src = xb + (size_t)c * LSEQ + (ok ? gl : 0);
        cpa4(base + (unsigned)((c * P1 + li) * 4), src, ok ? 4 : 0);
    }
}

// ---------------------------------------------------------------------------
// K1: shifted Grams via tf32 mma.sync (round-10 version, 37 CTAs, 1/SM).
// ---------------------------------------------------------------------------
__global__ __launch_bounds__(256, 1)
void k1_mma(const float* __restrict__ x)
{
    extern __shared__ float sm1[];
    float* xs0 = sm1;              // 64*P1 = 8448
    float* xs1 = sm1 + 8448;       // 8448

    const int tid = threadIdx.x, lane = tid & 31, w = tid >> 5;
    const int b = blockIdx.y, jx = blockIdx.x;
    const float* xb = x + (size_t)b * 64 * LSEQ;

    const int m0 = (w >> 1) * 16;
    const int n0 = (w & 1) * 32;
    const int g = lane >> 2, jj = lane & 3;

    float acc[12][4];
#pragma unroll
    for (int i = 0; i < 12; i++)
#pragma unroll
        for (int q = 0; q < 4; q++) acc[i][q] = 0.f;

    int t = jx;
    k1_fill(xs0, xb, t);
    cpa_commit();
    cpa_wait0();
    __syncthreads();

    float* cur = xs0;
    float* nxt = xs1;

    for (; t < NT1K; t += K1CTAS) {
        int tn = t + K1CTAS;
        if (tn < NT1K) k1_fill(nxt, xb, tn);
        cpa_commit();

        const float* xc = cur;
#pragma unroll 2
        for (int kc = 0; kc < T1 / 8; kc++) {
            const int k0 = kc * 8;
            const float* ar = xc + (m0 + g) * P1 + k0 + jj;
            unsigned a0 = __float_as_uint(ar[0]);
            unsigned a2 = __float_as_uint(ar[4]);
            unsigned a1 = __float_as_uint(ar[8 * P1]);
            unsigned a3 = __float_as_uint(ar[8 * P1 + 4]);
#pragma unroll
            for (int nt = 0; nt < 4; nt++) {
                const float* br = xc + (n0 + nt * 8 + g) * P1 + k0 + jj;
                unsigned v0 = __float_as_uint(br[0]);
                unsigned v1 = __float_as_uint(br[1]);
                unsigned v2 = __float_as_uint(br[2]);
                unsigned u0 = __float_as_uint(br[4]);
                unsigned u1 = __float_as_uint(br[5]);
                unsigned u2 = __float_as_uint(br[6]);
                mma8(acc[nt * 3 + 0], a0, a1, a2, a3, v0, u0);
                mma8(acc[nt * 3 + 1], a0, a1, a2, a3, v1, u1);
                mma8(acc[nt * 3 + 2], a0, a1, a2, a3, v2, u2);
            }
        }

        cpa_wait0();
        __syncthreads();
        float* tmp = cur; cur = nxt; nxt = tmp;
    }

    float* pb = g_part + ((size_t)(b * K1CTAS + jx) * 3) * 4096;
#pragma unroll
    for (int nt = 0; nt < 4; nt++)
#pragma unroll
        for (int s = 0; s < 3; s++) {
            const float* a = acc[nt * 3 + s];
            int col = n0 + nt * 8 + 2 * jj;
            int r0 = m0 + g;
            pb[s * 4096 + r0 * 64 + col]           = a[0];
            pb[s * 4096 + r0 * 64 + col + 1]       = a[1];
            pb[s * 4096 + (r0 + 8) * 64 + col]     = a[2];
            pb[s * 4096 + (r0 + 8) * 64 + col + 1] = a[3];
        }
}

// ---------------------------------------------------------------------------
// 64x64x64 matmul: C = A @ B (row-major smem); At=true -> C = A^T @ B
// ---------------------------------------------------------------------------
__device__ __forceinline__ void mm64(const float* __restrict__ A,
                                     const float* __restrict__ B,
                                     float* __restrict__ C, int tid, bool At)
{
    const int i0 = (tid >> 4) * 4, j0 = (tid & 15) * 4;
    float acc[4][4] = {};
    for (int k = 0; k < 64; k++) {
        float a[4];
#pragma unroll
        for (int i = 0; i < 4; i++) a[i] = At ? A[k * 64 + i0 + i] : A[(i0 + i) * 64 + k];
        float4 bv = *(const float4*)(B + k * 64 + j0);
        float bb[4] = {bv.x, bv.y, bv.z, bv.w};
#pragma unroll
        for (int i = 0; i < 4; i++)
#pragma unroll
            for (int j = 0; j < 4; j++) acc[i][j] = fmaf(a[i], bb[j], acc[i][j]);
    }
#pragma unroll
    for (int i = 0; i < 4; i++)
#pragma unroll
        for (int j = 0; j < 4; j++) C[(i0 + i) * 64 + j0 + j] = acc[i][j];
}

// ---------------------------------------------------------------------------
// K2a: reduce G_s; gd_s = diag(Wq G_s Wq^T); Z_s = G_s Wk^T (store); hd_s;
// if s>0 also Zt_s = G_s^T Wk^T.
// ---------------------------------------------------------------------------
__global__ __launch_bounds__(256)
void k2a(const float* __restrict__ w_kv, const float* __restrict__ w_q)
{
    extern __shared__ float sm2[];
    float* sG  = sm2;
    float* sWT = sm2 + 4096;
    float* sM  = sm2 + 8192;
    const int tid = threadIdx.x;
    const int s = blockIdx.x, b = blockIdx.y;

    for (int idx = tid; idx < 4096; idx += 256) {
        const float* p = g_part + ((size_t)(b * K1CTAS) * 3 + s) * 4096 + idx;
        float acc = 0.f;
        for (int blk = 0; blk < K1CTAS; blk++) acc += p[(size_t)blk * 3 * 4096];
        sG[idx] = acc;
    }
    for (int idx = tid; idx < 4096; idx += 256)
        sWT[(idx & 63) * 64 + (idx >> 6)] = w_q[idx];
    __syncthreads();

    mm64(sG, sWT, sM, tid, false);          // E = G_s @ Wq^T
    __syncthreads();
    if (tid < 64) {
        float acc = 0.f;
        for (int k = 0; k < 64; k++) acc = fmaf(sWT[k * 64 + tid], sM[k * 64 + tid], acc);
        g_gd[(b * 3 + s) * 64 + tid] = acc;
    }
    __syncthreads();

    for (int idx = tid; idx < 4096; idx += 256)
        sWT[(idx & 63) * 64 + (idx >> 6)] = w_kv[idx];   // Wk rows 0..63
    __syncthreads();

    mm64(sG, sWT, sM, tid, false);          // Z = G_s @ Wk^T
    __syncthreads();
    float* gZ = g_Z + (b * 5 + s) * 4096;
    for (int idx = tid; idx < 4096; idx += 256) gZ[idx] = sM[idx];
    if (tid < 64) {
        float acc = 0.f;
        for (int k = 0; k < 64; k++) acc = fmaf(sWT[k * 64 + tid], sM[k * 64 + tid], acc);
        g_hd[(b * 3 + s) * 64 + tid] = acc;
    }
    __syncthreads();

    if (s > 0) {
        mm64(sG, sWT, sM, tid, true);       // Zt = G_s^T @ Wk^T
        __syncthreads();
        float* gZt = g_Z + (b * 5 + 2 + s) * 4096;
        for (int idx = tid; idx < 4096; idx += 256) gZt[idx] = sM[idx];
    }
}

// ---------------------------------------------------------------------------
// K2b: assemble S (+ edge corrections), norms, softmax, P = Wproj @ attn.
// ---------------------------------------------------------------------------
__global__ __launch_bounds__(256)
void k2b(const float* __restrict__ x,
         const float* __restrict__ w_kv,
         const float* __restrict__ w_kv_dw,
         const float* __restrict__ w_q,
         const float* __restrict__ w_q_dw,
         const float* __restrict__ w_proj,
         const float* __restrict__ temperature)
{
    extern __shared__ float sm3[];
    float* sZ0  = sm3;
    float* sZ1  = sm3 + 4096;
    float* sZ2  = sm3 + 8192;
    float* sZ1t = sm3 + 12288;
    float* sZ2t = sm3 + 16384;
    float* sW   = sm3 + 20480;
    float* sR   = sm3 + 24576;
    float* sS   = sm3 + 28672;
    float* sP   = sm3 + 32768;

    __shared__ float x0s[64], xLs[64], u0s[64], uLs[64], v0s[64], vLs[64];
    __shared__ float aqs[3][64], bks[3][64], nqs[64], nks[64];

    const int tid = threadIdx.x;
    const int b = blockIdx.x;
    const float tempv = temperature[b];

    for (int idx = tid; idx < 5 * 4096; idx += 256) sm3[idx] = g_Z[b * 5 * 4096 + idx];
    for (int idx = tid; idx < 4096; idx += 256) sW[idx] = w_q[idx];
    if (tid < 64) {
        const int c = tid;
        x0s[c] = x[(b * 64 + c) * LSEQ];
        xLs[c] = x[(b * 64 + c) * LSEQ + LSEQ - 1];
#pragma unroll
        for (int e = 0; e < 3; e++) {
            aqs[e][c] = w_q_dw[c * 3 + e];
            bks[e][c] = w_kv_dw[c * 3 + e];
        }
    }
    __syncthreads();

    if (tid < 64) {
        const int c = tid;
        float a0 = 0.f, aL = 0.f, q0 = 0.f, qL = 0.f;
        for (int k = 0; k < 64; k++) {
            float wk = w_kv[c * 64 + k], wq = w_q[c * 64 + k];
            a0 = fmaf(wk, x0s[k], a0);  aL = fmaf(wk, xLs[k], aL);
            q0 = fmaf(wq, x0s[k], q0);  qL = fmaf(wq, xLs[k], qL);
        }
        u0s[c] = a0; uLs[c] = aL; v0s[c] = q0; vLs[c] = qL;
    }
    __syncthreads();

    for (int dd = 0; dd < 3; dd++) {
        for (int idx = tid; idx < 4096; idx += 256) {
            const int i = idx >> 6, j = idx & 63;
            float r;
            if (dd == 0) {
                r = (sZ0[idx] - xLs[i] * uLs[j]) * bks[0][j]
                  + sZ1[idx] * bks[1][j] + sZ2[idx] * bks[2][j];
            } else if (dd == 1) {
                r = sZ1t[idx] * bks[0][j] + sZ0[idx] * bks[1][j] + sZ1[idx] * bks[2][j];
            } else {
                r = sZ2t[idx] * bks[0][j] + sZ1t[idx] * bks[1][j]
                  + (sZ0[idx] - x0s[i] * u0s[j]) * bks[2][j];
            }
            sR[idx] = r;
        }
        __syncthreads();
        {
            const int i0 = (tid >> 4) * 4, j0 = (tid & 15) * 4;
            float acc[4][4] = {};
            for (int k = 0; k < 64; k++) {
                float a[4];
#pragma unroll
                for (int i = 0; i < 4; i++) a[i] = sW[(i0 + i) * 64 + k];
                float4 bv = *(const float4*)(sR + k * 64 + j0);
                float bb[4] = {bv.x, bv.y, bv.z, bv.w};
#pragma unroll
                for (int i = 0; i < 4; i++)
#pragma unroll
                    for (int j = 0; j < 4; j++) acc[i][j] = fmaf(a[i], bb[j], acc[i][j]);
            }
#pragma unroll
            for (int i = 0; i < 4; i++) {
                float scale = aqs[dd][i0 + i];
#pragma unroll
                for (int j = 0; j < 4; j++) {
                    if (dd == 0) sS[(i0 + i) * 64 + j0 + j] = scale * acc[i][j];
                    else         sS[(i0 + i) * 64 + j0 + j] += scale * acc[i][j];
                }
            }
        }
        __syncthreads();
    }

    if (tid < 64) {
        const int c = tid;
        float g0 = g_gd[(b * 3 + 0) * 64 + c], g1 = g_gd[(b * 3 + 1) * 64 + c],
              g2 = g_gd[(b * 3 + 2) * 64 + c];
        float h0 = g_hd[(b * 3 + 0) * 64 + c], h1 = g_hd[(b * 3 + 1) * 64 + c],
              h2 = g_hd[(b * 3 + 2) * 64 + c];
        float am = aqs[0][c], a0 = aqs[1][c], ap = aqs[2][c];
        float bm = bks[0][c], b0 = bks[1][c], bp = bks[2][c];
        float qq = am * am * (g0 - vLs[c] * vLs[c]) + a0 * a0 * g0
                 + ap * ap * (g0 - v0s[c] * v0s[c])
                 + 2.f * (am * a0 + a0 * ap) * g1 + 2.f * am * ap * g2;
        float kk = bm * bm * (h0 - uLs[c] * uLs[c]) + b0 * b0 * h0
                 + bp * bp * (h0 - u0s[c] * u0s[c])
                 + 2.f * (bm * b0 + b0 * bp) * h1 + 2.f * bm * bp * h2;
        nqs[c] = fmaxf(sqrtf(qq), 1e-12f);
        nks[c] = fmaxf(sqrtf(kk), 1e-12f);
    }
    __syncthreads();

    for (int idx = tid; idx < 4096; idx += 256) {
        const int i = idx >> 6, j = idx & 63;
        sS[idx] = tempv * sS[idx] / (nqs[i] * nks[j]);
    }
    __syncthreads();

    if (tid < 64) {
        const int c = tid;
        float m = -1e30f;
        for (int j = 0; j < 64; j++) m = fmaxf(m, sS[c * 64 + j]);
        float sum = 0.f;
        for (int j = 0; j < 64; j++) {
            float e = expf(sS[c * 64 + j] - m);
            sS[c * 64 + j] = e; sum += e;
        }
        float inv = 1.f / sum;
        for (int j = 0; j < 64; j++) sS[c * 64 + j] *= inv;
    }
    __syncthreads();
    for (int idx = tid; idx < 4096; idx += 256) sW[idx] = w_proj[idx];
    __syncthreads();

    mm64(sW, sS, sP, tid, false);
    __syncthreads();
    for (int idx = tid; idx < 4096; idx += 256) g_P[b * 4096 + idx] = sP[idx];
}

// ---------------------------------------------------------------------------
// K3: 512 threads, 1 CTA/SM (round-10 base) with shuffle-fused dwconv:
// GEMM1 keeps y in regs; neighbors' y via __shfl_down; v written straight to
// the v buffer. 2 barriers/tile instead of 3; no yv SMEM round-trip.
// ---------------------------------------------------------------------------
__device__ __forceinline__ void load_tile_async(float* dst, const float* xb, int t)
{
    const int tid = threadIdx.x;
    const int l0 = t * TT - 1;
    unsigned base = s2u(dst);
    for (int idx = tid; idx < 64 * 130; idx += 512) {
        int c = idx / 130;
        int li = idx - c * 130;
        int gl = l0 + li;
        int ok = (gl >= 0) && (gl < LSEQ);
        const float* src = xb + (size_t)c * LSEQ + (ok ? gl : 0);
        cpa4(base + (unsigned)((c * 132 + li) * 4), src, ok ? 4 : 0);
    }
}

__global__ __launch_bounds__(512, 1)
void k3_out(const float* __restrict__ x,
            const float* __restrict__ w_kv,
            const float* __restrict__ w_kv_dw,
            float* __restrict__ out)
{
    extern __shared__ float sm4[];
    float* xs0 = sm4;             // 8448  x ping
    float* xs1 = sm4 + 8448;      // 8448  x pong
    float* vb  = sm4 + 16896;     // 8448  v buffer
    float* wsv = sm4 + 25344;     // 4352  [k][o]
    float* ps  = sm4 + 29696;     // 4352  [c][o]
    float* wdv = sm4 + 34048;     // 192
    // total 34240 floats = 136960 B

    const int tid = threadIdx.x;
    const int b = blockIdx.y;
    const float* xb = x + (size_t)b * 64 * LSEQ;

    for (int idx = tid; idx < 4096; idx += 512) {
        int o = idx >> 6, k = idx & 63;
        wsv[k * 68 + o] = w_kv[(64 + o) * 64 + k];   // Wv rows 64..127
        ps[k * 68 + o]  = g_P[b * 4096 + idx];       // ps[c][o] = P[o][c]
    }
    for (int idx = tid; idx < 192; idx += 512)
        wdv[idx] = w_kv_dw[192 + idx];

    int t = blockIdx.x;
    if (t < NTILES) load_tile_async(xs0, xb, t);
    cpa_commit();
    cpa_wait0();
    __syncthreads();

    const int o0 = (tid >> 5) * 4;       // 16 o-blocks
    const int lB = (tid & 31) * 4;       // 32 l-blocks (adjacent lanes!)

    // depthwise weights for this thread's 4 output rows, preloaded
    float wd[4][3];
#pragma unroll
    for (int i = 0; i < 4; i++) {
        wd[i][0] = wdv[(o0 + i) * 3];
        wd[i][1] = wdv[(o0 + i) * 3 + 1];
        wd[i][2] = wdv[(o0 + i) * 3 + 2];
    }

    float* cur = xs0;
    float* nxt = xs1;

    for (; t < NTILES; t += G3X) {
        int tn = t + G3X;
        if (tn < NTILES) load_tile_async(nxt, xb, tn);
        cpa_commit();

        // GEMM1: y = Wv @ x, kept in registers
        u64 acc[4][2];
#pragma unroll
        for (int i = 0; i < 4; i++) { acc[i][0] = 0ull; acc[i][1] = 0ull; }
#pragma unroll 4
        for (int k = 0; k < 64; k++) {
            float4 av = *(const float4*)(wsv + k * 68 + o0);
            u64 a0 = dup2(av.x), a1 = dup2(av.y), a2 = dup2(av.z), a3 = dup2(av.w);
            ulonglong2 bv = *(const ulonglong2*)(cur + k * 132 + lB);
            fma2(acc[0][0], a0, bv.x); fma2(acc[0][1], a0, bv.y);
            fma2(acc[1][0], a1, bv.x); fma2(acc[1][1], a1, bv.y);
            fma2(acc[2][0], a2, bv.x); fma2(acc[2][1], a2, bv.y);
            fma2(acc[3][0], a3, bv.x); fma2(acc[3][1], a3, bv.y);
        }

        // dwconv fused via shuffle: y[lB+4], y[lB+5] from lane+1
#pragma unroll
        for (int i = 0; i < 4; i++) {
            u64 up = __shfl_down_sync(0xffffffffu, acc[i][0], 1);
            float2 y01 = unpack2(acc[i][0]);
            float2 y23 = unpack2(acc[i][1]);
            float2 y45 = unpack2(up);
            float2 va, vbv;
            va.x  = wd[i][0] * y01.x + wd[i][1] * y01.y + wd[i][2] * y23.x;
            va.y  = wd[i][0] * y01.y + wd[i][1] * y23.x + wd[i][2] * y23.y;
            vbv.x = wd[i][0] * y23.x + wd[i][1] * y23.y + wd[i][2] * y45.x;
            vbv.y = wd[i][0] * y23.y + wd[i][1] * y45.x + wd[i][2] * y45.y;
            *(float2*)(vb + (o0 + i) * 132 + lB)     = va;
            *(float2*)(vb + (o0 + i) * 132 + lB + 2) = vbv;
        }
        __syncthreads();

        // GEMM2: out = P @ v, direct store
        {
            u64 oacc[4][2];
#pragma unroll
            for (int i = 0; i < 4; i++) { oacc[i][0] = 0ull; oacc[i][1] = 0ull; }
#pragma unroll 4
            for (int c = 0; c < 64; c++) {
                float4 av = *(const float4*)(ps + c * 68 + o0);
                u64 a0 = dup2(av.x), a1 = dup2(av.y), a2 = dup2(av.z), a3 = dup2(av.w);
                ulonglong2 bv = *(const ulonglong2*)(vb + c * 132 + lB);
                fma2(oacc[0][0], a0, bv.x); fma2(oacc[0][1], a0, bv.y);
                fma2(oacc[1][0], a1, bv.x); fma2(oacc[1][1], a1, bv.y);
                fma2(oacc[2][0], a2, bv.x); fma2(oacc[2][1], a2, bv.y);
                fma2(oacc[3][0], a3, bv.x); fma2(oacc[3][1], a3, bv.y);
            }
            const int gl = t * TT + lB;
            const bool ok0 = (gl < LSEQ);                   // lB <= 124
            const bool ok1 = (lB != 124) && (gl + 2 < LSEQ);
#pragma unroll
            for (int i = 0; i < 4; i++) {
                float* op = out + (size_t)(b * 64 + o0 + i) * LSEQ;
                if (ok0) *(float2*)(op + gl)     = unpack2(oacc[i][0]);
                if (ok1) *(float2*)(op + gl + 2) = unpack2(oacc[i][1]);
            }
        }

        cpa_wait0();
        __syncthreads();
        float* tmp = cur; cur = nxt; nxt = tmp;
    }
}

// ---------------------------------------------------------------------------
extern "C" void kernel_launch(void* const* d_in, const int* in_sizes, int n_in,
                              void* d_out, int out_size)
{
    const float* x           = (const float*)d_in[0];
    const float* w_kv        = (const float*)d_in[1];
    const float* w_kv_dw     = (const float*)d_in[2];
    const float* w_q         = (const float*)d_in[3];
    const float* w_q_dw      = (const float*)d_in[4];
    const float* w_proj      = (const float*)d_in[5];
    const float* temperature = (const float*)d_in[6];
    float* out = (float*)d_out;

    const int SM1  = 2 * 8448 * 4;      // 67584
    const int SM2A = 3 * 4096 * 4;
    const int SM2B = 9 * 4096 * 4;
    const int SM3  = 34240 * 4;         // 136960
    cudaFuncSetAttribute(k1_mma, cudaFuncAttributeMaxDynamicSharedMemorySize, SM1);
    cudaFuncSetAttribute(k2a,    cudaFuncAttributeMaxDynamicSharedMemorySize, SM2A);
    cudaFuncSetAttribute(k2b,    cudaFuncAttributeMaxDynamicSharedMemorySize, SM2B);
    cudaFuncSetAttribute(k3_out, cudaFuncAttributeMaxDynamicSharedMemorySize, SM3);

    k1_mma<<<dim3(K1CTAS, NB), 256, SM1>>>(x);
    k2a<<<dim3(3, NB), 256, SM2A>>>(w_kv, w_q);
    k2b<<<NB, 256, SM2B>>>(x, w_kv, w_kv_dw, w_q, w_q_dw, w_proj, temperature);
    k3_out<<<dim3(G3X, NB), 512, SM3>>>(x, w_kv, w_kv_dw, out);
}